// round 2
// baseline (speedup 1.0000x reference)
#include <cuda_runtime.h>

// Problem constants
#define TOKENS   65536          // 16*64*64
#define DDIM     256
#define KCODES   1024
#define Z_ELEMS  (TOKENS * DDIM)   // 16777216
#define BETA     0.25f
#define EPS_F    1e-5f

// Argmin kernel tiling
#define TT   64     // tokens per CTA
#define KC   128    // code chunk
#define DC   64     // d chunk per smem stage
#define NBLK_A   (TOKENS / TT)   // 1024
#define NBLK_B   4096            // gather/loss blocks

// Output layout (flattened reference tuple, float32):
//   [0 .. Z_ELEMS)                 z_q_st
//   [Z_ELEMS + 0]                  commitment_loss
//   [Z_ELEMS + 1]                  codebook_loss
//   [Z_ELEMS + 2]                  cluster_loss
//   [Z_ELEMS + 3]                  perplexity
//   [Z_ELEMS + 4 .. +4+TOKENS)     indices (cast to float)

// Scratch (device globals: no allocations allowed)
__device__ int     g_indices[TOKENS];
__device__ int     g_counts[KCODES];
__device__ double  g_partial[NBLK_B];
__device__ float   g_e2[KCODES];
__device__ float   g_z2[TOKENS];
__device__ float2  g_ctp[(DDIM / 2) * KCODES];   // [d/2][k] pairs (e[k][2dp], e[k][2dp+1])

// ---------------------------------------------------------------------------
// init: zero the histogram (graph replays reuse globals)
// ---------------------------------------------------------------------------
__global__ void vq_init_kernel() {
    int i = blockIdx.x * blockDim.x + threadIdx.x;
    if (i < KCODES) g_counts[i] = 0;
}

// ---------------------------------------------------------------------------
// prep codebook: e2[k] (mul-then-add, mimicking jnp.sum(e*e)) and the
// transposed-paired layout g_ctp[dp][k].
// ---------------------------------------------------------------------------
__global__ void vq_prep_cb_kernel(const float* __restrict__ cb) {
    int k = blockIdx.x * blockDim.x + threadIdx.x;
    if (k >= KCODES) return;
    const float* row = cb + (size_t)k * DDIM;
    float s = 0.0f;
    for (int d = 0; d < DDIM; d += 2) {
        float a = row[d];
        float b = row[d + 1];
        s = __fadd_rn(s, __fmul_rn(a, a));
        s = __fadd_rn(s, __fmul_rn(b, b));
        g_ctp[(d >> 1) * KCODES + k] = make_float2(a, b);
    }
    g_e2[k] = s;
}

// ---------------------------------------------------------------------------
// prep z2: per-token ||z||^2, sequential mul-then-add over d.
// ---------------------------------------------------------------------------
__global__ void vq_prep_z2_kernel(const float* __restrict__ z) {
    int t = blockIdx.x * blockDim.x + threadIdx.x;
    if (t >= TOKENS) return;
    const float4* row = reinterpret_cast<const float4*>(z) + (size_t)t * (DDIM / 4);
    float s = 0.0f;
    #pragma unroll 8
    for (int i = 0; i < DDIM / 4; i++) {
        float4 v = row[i];
        s = __fadd_rn(s, __fmul_rn(v.x, v.x));
        s = __fadd_rn(s, __fmul_rn(v.y, v.y));
        s = __fadd_rn(s, __fmul_rn(v.z, v.z));
        s = __fadd_rn(s, __fmul_rn(v.w, v.w));
    }
    g_z2[t] = s;
}

// ---------------------------------------------------------------------------
// argmin kernel: each CTA = 64 tokens x all 1024 codes.
//   smem: zs[64][256] floats (64KB, loaded once) + es2[32][128] f32x2 (32KB/stage)
//   thread tile: 4 tokens x 8 codes, f32x2 accumulators over (even d, odd d).
//   dist = fl( fl(z2 + e2) - 2*ze ), first-index tie break.
// ---------------------------------------------------------------------------
__global__ void __launch_bounds__(256, 2)
vq_argmin(const float* __restrict__ z, float* __restrict__ out_idx_f) {
    extern __shared__ float smem[];
    float* zs = smem;                                            // TT*DDIM floats (64KB)
    unsigned long long* es2 =
        reinterpret_cast<unsigned long long*>(smem + TT * DDIM); // (DC/2)*KC u64 (32KB)

    const int tid  = threadIdx.x;
    const int tok0 = blockIdx.x * TT;
    const int cg   = tid & 15;    // code group  (0..15)
    const int ttg  = tid >> 4;    // token group (0..15) -> tokens ttg*4 .. ttg*4+3

    // Load z tile: 4096 float4s, 16 per thread, coalesced.
    {
        const float4* zg  = reinterpret_cast<const float4*>(z);
        float4*       zs4 = reinterpret_cast<float4*>(zs);
        #pragma unroll
        for (int p = 0; p < 16; p++) {
            int idx = tid + p * 256;          // 0..4095
            int r   = idx >> 6;               // token row 0..63
            int c4  = idx & 63;               // float4 col 0..63
            zs4[r * (DDIM / 4) + c4] = zg[(size_t)(tok0 + r) * (DDIM / 4) + c4];
        }
    }

    float z2r[4];
    #pragma unroll
    for (int i = 0; i < 4; i++) z2r[i] = g_z2[tok0 + ttg * 4 + i];

    float best[4];
    int   bidx[4];
    #pragma unroll
    for (int i = 0; i < 4; i++) { best[i] = 3.4e38f; bidx[i] = 0; }

    const unsigned long long* ctp_u =
        reinterpret_cast<const unsigned long long*>(g_ctp);

    for (int kc = 0; kc < KCODES; kc += KC) {
        unsigned long long acc[4][8];
        #pragma unroll
        for (int i = 0; i < 4; i++)
            #pragma unroll
            for (int j = 0; j < 8; j++) acc[i][j] = 0ull;

        for (int dc = 0; dc < DDIM; dc += DC) {
            __syncthreads();
            // stage es2[dp][c] = ctp[(dc/2 + dp)][kc + c], coalesced 8B.
            #pragma unroll
            for (int p = 0; p < 16; p++) {
                int idx = tid + p * 256;        // 0..4095
                int dp  = idx >> 7;             // 0..31
                int c   = idx & 127;            // 0..127
                es2[dp * KC + c] = ctp_u[(size_t)((dc >> 1) + dp) * KCODES + kc + c];
            }
            __syncthreads();

            const float* zrow0 = zs + (ttg * 4) * DDIM + dc;
            #pragma unroll 4
            for (int dp = 0; dp < DC / 2; ++dp) {
                unsigned long long za[4];
                #pragma unroll
                for (int i = 0; i < 4; i++)
                    za[i] = *reinterpret_cast<const unsigned long long*>(
                        zrow0 + i * DDIM + 2 * dp);
                #pragma unroll
                for (int j = 0; j < 8; j++) {
                    unsigned long long eb = es2[dp * KC + cg + j * 16];
                    #pragma unroll
                    for (int i = 0; i < 4; i++)
                        asm volatile("fma.rn.f32x2 %0, %1, %2, %0;"
                                     : "+l"(acc[i][j]) : "l"(za[i]), "l"(eb));
                }
            }
        }

        // chunk epilogue: dist + running argmin (ascending k per thread)
        #pragma unroll
        for (int j = 0; j < 8; j++) {
            int k = kc + cg + j * 16;
            float e2k = g_e2[k];
            #pragma unroll
            for (int i = 0; i < 4; i++) {
                float lo = __uint_as_float((unsigned)(acc[i][j] & 0xFFFFFFFFull));
                float hi = __uint_as_float((unsigned)(acc[i][j] >> 32));
                float ze = __fadd_rn(lo, hi);
                float dist = __fsub_rn(__fadd_rn(z2r[i], e2k), __fmul_rn(2.0f, ze));
                if (dist < best[i]) { best[i] = dist; bidx[i] = k; }
            }
        }
    }

    // cross-thread reduce (16 code groups per token), reuse zs region.
    __syncthreads();
    float* sdist = smem;                               // 64*16 floats
    int*   sidx  = reinterpret_cast<int*>(smem + TT * 16);
    #pragma unroll
    for (int i = 0; i < 4; i++) {
        int t = ttg * 4 + i;
        sdist[t * 16 + cg] = best[i];
        sidx [t * 16 + cg] = bidx[i];
    }
    __syncthreads();
    if (tid < TT) {
        int t = tid;
        float bd = sdist[t * 16];
        int   bi = sidx [t * 16];
        #pragma unroll
        for (int c = 1; c < 16; c++) {
            float d2 = sdist[t * 16 + c];
            int   i2 = sidx [t * 16 + c];
            if (d2 < bd || (d2 == bd && i2 < bi)) { bd = d2; bi = i2; }
        }
        int gt = tok0 + t;
        g_indices[gt] = bi;
        out_idx_f[gt] = (float)bi;
        atomicAdd(&g_counts[bi], 1);
    }
}

// ---------------------------------------------------------------------------
// gather z_q, write z_q_st = fl(z + fl(zq - z)), accumulate loss partials.
// ---------------------------------------------------------------------------
__global__ void vq_gather_loss(const float* __restrict__ z,
                               const float* __restrict__ cb,
                               float* __restrict__ out) {
    __shared__ double sred[256];
    const int tid = threadIdx.x;
    double s = 0.0;
    const float4* z4  = reinterpret_cast<const float4*>(z);
    const float4* cb4 = reinterpret_cast<const float4*>(cb);
    float4*       o4  = reinterpret_cast<float4*>(out);

    int base = blockIdx.x * 256 * 4;  // float4 index base; NBLK_B*1024 = 4194304 total
    #pragma unroll
    for (int q = 0; q < 4; q++) {
        int e4 = base + q * 256 + tid;
        int t  = e4 >> 6;          // token
        int d4 = e4 & 63;          // float4 within row
        int idx = g_indices[t];
        float4 zq = cb4[(size_t)idx * 64 + d4];
        float4 zz = z4[e4];
        float4 o;
        o.x = __fadd_rn(zz.x, __fsub_rn(zq.x, zz.x));
        o.y = __fadd_rn(zz.y, __fsub_rn(zq.y, zz.y));
        o.z = __fadd_rn(zz.z, __fsub_rn(zq.z, zz.z));
        o.w = __fadd_rn(zz.w, __fsub_rn(zq.w, zz.w));
        o4[e4] = o;
        float dx = __fsub_rn(zz.x, zq.x);
        float dy = __fsub_rn(zz.y, zq.y);
        float dz = __fsub_rn(zz.z, zq.z);
        float dw = __fsub_rn(zz.w, zq.w);
        s += (double)__fmul_rn(dx, dx);
        s += (double)__fmul_rn(dy, dy);
        s += (double)__fmul_rn(dz, dz);
        s += (double)__fmul_rn(dw, dw);
    }
    sred[tid] = s;
    __syncthreads();
    for (int stride = 128; stride > 0; stride >>= 1) {
        if (tid < stride) sred[tid] += sred[tid + stride];
        __syncthreads();
    }
    if (tid == 0) g_partial[blockIdx.x] = sred[0];
}

// ---------------------------------------------------------------------------
// finalize: scalars (deterministic sequential sums).
// ---------------------------------------------------------------------------
__global__ void vq_finalize(float* __restrict__ out) {
    if (threadIdx.x != 0 || blockIdx.x != 0) return;
    double S = 0.0;
    for (int b = 0; b < NBLK_B; b++) S += g_partial[b];
    float L = (float)(S / (double)Z_ELEMS);
    out[Z_ELEMS + 0] = L;                                   // commitment_loss
    out[Z_ELEMS + 1] = L;                                   // codebook_loss
    out[Z_ELEMS + 2] = __fadd_rn(L, __fmul_rn(BETA, L));    // cluster_loss
    // perplexity
    float tot = 0.0f;
    for (int k = 0; k < KCODES; k++) tot = __fadd_rn(tot, (float)g_counts[k]);
    float denom = __fadd_rn(tot, EPS_F);
    float H = 0.0f;
    for (int k = 0; k < KCODES; k++) {
        float p = __fdiv_rn((float)g_counts[k], denom);
        H = __fadd_rn(H, __fmul_rn(p, __logf(__fadd_rn(p, EPS_F))));
    }
    out[Z_ELEMS + 3] = __expf(-H);
}

// ---------------------------------------------------------------------------
extern "C" void kernel_launch(void* const* d_in, const int* in_sizes, int n_in,
                              void* d_out, int out_size) {
    const float* z  = (const float*)d_in[0];   // [65536, 256]
    const float* cb = (const float*)d_in[1];   // [1024, 256]
    float* out = (float*)d_out;

    static_assert(TT * DDIM * 4 + (DC / 2) * KC * 8 == 98304, "smem size");
    cudaFuncSetAttribute(vq_argmin, cudaFuncAttributeMaxDynamicSharedMemorySize, 98304);

    vq_init_kernel<<<4, 256>>>();
    vq_prep_cb_kernel<<<4, 256>>>(cb);
    vq_prep_z2_kernel<<<TOKENS / 256, 256>>>(z);
    vq_argmin<<<NBLK_A, 256, 98304>>>(z, out + Z_ELEMS + 4);
    vq_gather_loss<<<NBLK_B, 256>>>(z, cb, out);
    vq_finalize<<<1, 1>>>(out);
}

// round 3
// speedup vs baseline: 1.3890x; 1.3890x over previous
#include <cuda_runtime.h>

// Problem constants
#define TOKENS   65536          // 16*64*64
#define DDIM     256
#define KCODES   1024
#define Z_ELEMS  (TOKENS * DDIM)   // 16777216
#define BETA     0.25f
#define EPS_F    1e-5f

// Argmin kernel tiling
#define TT       64     // tokens per CTA
#define KC       128    // code chunk
#define DC       32     // d chunk per smem stage
#define NSTAGES  ((KCODES / KC) * (DDIM / DC))   // 64
#define NBLK_A   (TOKENS / TT)   // 1024

// Output layout (flattened reference tuple, float32):
//   [0 .. Z_ELEMS)                 z_q_st
//   [Z_ELEMS + 0]                  commitment_loss
//   [Z_ELEMS + 1]                  codebook_loss
//   [Z_ELEMS + 2]                  cluster_loss
//   [Z_ELEMS + 3]                  perplexity
//   [Z_ELEMS + 4 .. +4+TOKENS)     indices (cast to float)

// Scratch (device globals: no allocations allowed)
__device__ int        g_indices[TOKENS];
__device__ int        g_counts[KCODES];
__device__ double     g_partial[NBLK_A];
__device__ float      g_e2[KCODES];
__device__ float      g_z2[TOKENS];
// codebook repacked: [d/4][k], each entry = {pack(e[4q],e[4q+1]), pack(e[4q+2],e[4q+3])}
__device__ ulonglong2 g_ctp4[(DDIM / 4) * KCODES];

// ---------------------------------------------------------------------------
// init: zero the histogram (graph replays reuse globals)
// ---------------------------------------------------------------------------
__global__ void vq_init_kernel() {
    int i = blockIdx.x * blockDim.x + threadIdx.x;
    if (i < KCODES) g_counts[i] = 0;
}

// ---------------------------------------------------------------------------
// prep codebook: e2[k] (sequential mul-then-add, same order as reference) and
// the quad-packed transposed layout g_ctp4[d/4][k].
// ---------------------------------------------------------------------------
__global__ void vq_prep_cb_kernel(const float* __restrict__ cb) {
    int k = blockIdx.x * blockDim.x + threadIdx.x;
    if (k >= KCODES) return;
    const float* row = cb + (size_t)k * DDIM;
    float s = 0.0f;
    for (int d = 0; d < DDIM; d += 4) {
        float a = row[d], b = row[d + 1], c = row[d + 2], e = row[d + 3];
        s = __fadd_rn(s, __fmul_rn(a, a));
        s = __fadd_rn(s, __fmul_rn(b, b));
        s = __fadd_rn(s, __fmul_rn(c, c));
        s = __fadd_rn(s, __fmul_rn(e, e));
        float2 p01 = make_float2(a, b);
        float2 p23 = make_float2(c, e);
        ulonglong2 v;
        v.x = *reinterpret_cast<unsigned long long*>(&p01);
        v.y = *reinterpret_cast<unsigned long long*>(&p23);
        g_ctp4[(d >> 2) * KCODES + k] = v;
    }
    g_e2[k] = s;
}

// ---------------------------------------------------------------------------
// prep z2: per-token ||z||^2 with the SAME sequential mul-then-add order as
// the reference, but coalesced loads via a padded smem transpose (stride 257
// -> conflict-free strided reads in the summing phase).
// ---------------------------------------------------------------------------
__global__ void __launch_bounds__(256) vq_prep_z2_kernel(const float* __restrict__ z) {
    __shared__ float zt[32 * 257];
    const int tid  = threadIdx.x;
    const int tok0 = blockIdx.x * 32;
    const float* zb = z + (size_t)tok0 * DDIM;
    #pragma unroll
    for (int p = 0; p < 32; p++) {
        int e = tid + p * 256;        // 0..8191
        int t = e >> 8;               // 0..31
        int d = e & 255;
        zt[t * 257 + d] = zb[e];
    }
    __syncthreads();
    if (tid < 32) {
        const float* row = &zt[tid * 257];
        float s = 0.0f;
        #pragma unroll 8
        for (int d = 0; d < DDIM; d++)
            s = __fadd_rn(s, __fmul_rn(row[d], row[d]));
        g_z2[tok0 + tid] = s;
    }
}

// ---------------------------------------------------------------------------
// argmin kernel (fused): each CTA = 64 tokens x all 1024 codes.
//   smem: zs[64][256] floats (64KB, loaded once)
//         es[2][8][128] ulonglong2 (2 x 16KB double-buffered code stages)
//   cp.async prefetches stage s+1 while computing stage s.
//   thread tile: 4 tokens x 8 codes, f32x2 accumulators (even d, odd d).
//   dist = fl( fl(z2 + e2) - 2*ze ), first-index tie break (same as R2).
//   Fused epilogue: cross-thread argmin reduce, index write, histogram,
//   z_q_st gather+write, loss partial — all without re-reading z.
// ---------------------------------------------------------------------------
__global__ void __launch_bounds__(256, 2)
vq_argmin(const float* __restrict__ z, const float* __restrict__ cb,
          float* __restrict__ out) {
    extern __shared__ float smem[];
    float* zs = smem;                                              // 16384 floats
    ulonglong2* es = reinterpret_cast<ulonglong2*>(smem + TT * DDIM); // 2048 ul2

    const int tid  = threadIdx.x;
    const int tok0 = blockIdx.x * TT;
    const int cg   = tid & 15;    // code group  (0..15)
    const int ttg  = tid >> 4;    // token group (0..15) -> tokens ttg*4..+3

    // Load z tile: 4096 float4s, 16 per thread, coalesced.
    {
        const float4* zg  = reinterpret_cast<const float4*>(z);
        float4*       zs4 = reinterpret_cast<float4*>(zs);
        #pragma unroll
        for (int p = 0; p < 16; p++) {
            int idx = tid + p * 256;
            zs4[idx] = zg[(size_t)tok0 * (DDIM / 4) + idx];
        }
    }

    float z2r[4];
    #pragma unroll
    for (int i = 0; i < 4; i++) z2r[i] = g_z2[tok0 + ttg * 4 + i];

    float best[4];
    int   bidx[4];
    #pragma unroll
    for (int i = 0; i < 4; i++) { best[i] = 3.4e38f; bidx[i] = 0; }

    // --- stage prefetch helper (cp.async, 4 x 16B per thread) ---
    #define STAGE_LOAD(S, BUF)                                                   \
    do {                                                                         \
        int kc_ = ((S) >> 3) * KC;                                               \
        int dc_ = ((S) & 7) * DC;                                                \
        _Pragma("unroll")                                                        \
        for (int q = 0; q < 4; q++) {                                            \
            int idx_ = tid + q * 256;                                            \
            int dph_ = idx_ >> 7;                                                \
            int c_   = idx_ & 127;                                               \
            const ulonglong2* src_ =                                             \
                &g_ctp4[(size_t)((dc_ >> 2) + dph_) * KCODES + kc_ + c_];        \
            unsigned dst_ = (unsigned)__cvta_generic_to_shared(                  \
                &es[(BUF) * 1024 + idx_]);                                       \
            asm volatile("cp.async.cg.shared.global [%0], [%1], 16;\n"           \
                         :: "r"(dst_), "l"(src_));                               \
        }                                                                        \
        asm volatile("cp.async.commit_group;\n" ::: "memory");                   \
    } while (0)

    STAGE_LOAD(0, 0);

    unsigned long long acc[4][8];
    int buf = 0;

    for (int s = 0; s < NSTAGES; s++) {
        if ((s & 7) == 0) {
            #pragma unroll
            for (int i = 0; i < 4; i++)
                #pragma unroll
                for (int j = 0; j < 8; j++) acc[i][j] = 0ull;
        }

        asm volatile("cp.async.wait_group 0;\n" ::: "memory");
        __syncthreads();
        if (s + 1 < NSTAGES) STAGE_LOAD(s + 1, buf ^ 1);

        const int dc = (s & 7) * DC;
        const ulonglong2* eb_base = &es[buf * 1024];
        const float* zrow0 = zs + (ttg * 4) * DDIM + dc;

        #pragma unroll
        for (int dph = 0; dph < 8; dph++) {
            ulonglong2 za[4];
            #pragma unroll
            for (int i = 0; i < 4; i++)
                za[i] = *reinterpret_cast<const ulonglong2*>(
                    zrow0 + i * DDIM + 4 * dph);
            #pragma unroll
            for (int j = 0; j < 8; j++) {
                ulonglong2 eb = eb_base[dph * KC + cg + j * 16];
                #pragma unroll
                for (int i = 0; i < 4; i++) {
                    asm volatile("fma.rn.f32x2 %0, %1, %2, %0;"
                                 : "+l"(acc[i][j]) : "l"(za[i].x), "l"(eb.x));
                    asm volatile("fma.rn.f32x2 %0, %1, %2, %0;"
                                 : "+l"(acc[i][j]) : "l"(za[i].y), "l"(eb.y));
                }
            }
        }
        buf ^= 1;

        if ((s & 7) == 7) {
            // per-kc epilogue: dist + running argmin (ascending k per thread)
            int kc = (s >> 3) * KC;
            #pragma unroll
            for (int j = 0; j < 8; j++) {
                int k = kc + cg + j * 16;
                float e2k = g_e2[k];
                #pragma unroll
                for (int i = 0; i < 4; i++) {
                    float lo = __uint_as_float((unsigned)(acc[i][j] & 0xFFFFFFFFull));
                    float hi = __uint_as_float((unsigned)(acc[i][j] >> 32));
                    float ze = __fadd_rn(lo, hi);
                    float dist = __fsub_rn(__fadd_rn(z2r[i], e2k),
                                           __fmul_rn(2.0f, ze));
                    if (dist < best[i]) { best[i] = dist; bidx[i] = k; }
                }
            }
        }
    }
    #undef STAGE_LOAD

    // --- final cross-thread argmin reduce (es region is free now) ---
    __syncthreads();
    float*  sdist = smem + TT * DDIM;                 // 1024 floats
    int*    sidx  = reinterpret_cast<int*>(sdist + 1024);
    int*    sfin  = reinterpret_cast<int*>(sdist + 2048);
    double* dred  = reinterpret_cast<double*>(sdist + 2304);  // 8B-aligned

    #pragma unroll
    for (int i = 0; i < 4; i++) {
        int t = ttg * 4 + i;
        sdist[t * 16 + cg] = best[i];
        sidx [t * 16 + cg] = bidx[i];
    }
    __syncthreads();
    if (tid < TT) {
        int t = tid;
        float bd = sdist[t * 16];
        int   bi = sidx [t * 16];
        #pragma unroll
        for (int c = 1; c < 16; c++) {
            float d2 = sdist[t * 16 + c];
            int   i2 = sidx [t * 16 + c];
            if (d2 < bd || (d2 == bd && i2 < bi)) { bd = d2; bi = i2; }
        }
        int gt = tok0 + t;
        g_indices[gt] = bi;
        out[Z_ELEMS + 4 + gt] = (float)bi;
        atomicAdd(&g_counts[bi], 1);
        sfin[t] = bi;
    }
    __syncthreads();

    // --- fused gather + z_q_st write + loss partial (z tile still in smem) ---
    double sacc = 0.0;
    const float4* cb4 = reinterpret_cast<const float4*>(cb);
    const float4* zs4 = reinterpret_cast<const float4*>(zs);
    float4*       o4  = reinterpret_cast<float4*>(out);
    #pragma unroll
    for (int p = 0; p < 16; p++) {
        int e4 = tid + p * 256;           // 0..4095
        int t  = e4 >> 6;
        int d4 = e4 & 63;
        int idx = sfin[t];
        float4 zq = cb4[(size_t)idx * (DDIM / 4) + d4];
        float4 zz = zs4[e4];
        float4 o;
        o.x = __fadd_rn(zz.x, __fsub_rn(zq.x, zz.x));
        o.y = __fadd_rn(zz.y, __fsub_rn(zq.y, zz.y));
        o.z = __fadd_rn(zz.z, __fsub_rn(zq.z, zz.z));
        o.w = __fadd_rn(zz.w, __fsub_rn(zq.w, zz.w));
        o4[(size_t)tok0 * (DDIM / 4) + e4] = o;
        float dx = __fsub_rn(zz.x, zq.x);
        float dy = __fsub_rn(zz.y, zq.y);
        float dz = __fsub_rn(zz.z, zq.z);
        float dw = __fsub_rn(zz.w, zq.w);
        sacc += (double)__fmul_rn(dx, dx);
        sacc += (double)__fmul_rn(dy, dy);
        sacc += (double)__fmul_rn(dz, dz);
        sacc += (double)__fmul_rn(dw, dw);
    }
    dred[tid] = sacc;
    __syncthreads();
    for (int stride = 128; stride > 0; stride >>= 1) {
        if (tid < stride) dred[tid] += dred[tid + stride];
        __syncthreads();
    }
    if (tid == 0) g_partial[blockIdx.x] = dred[0];
}

// ---------------------------------------------------------------------------
// finalize: scalars (deterministic sequential sums).
// ---------------------------------------------------------------------------
__global__ void vq_finalize(float* __restrict__ out) {
    if (threadIdx.x != 0 || blockIdx.x != 0) return;
    double S = 0.0;
    for (int b = 0; b < NBLK_A; b++) S += g_partial[b];
    float L = (float)(S / (double)Z_ELEMS);
    out[Z_ELEMS + 0] = L;                                   // commitment_loss
    out[Z_ELEMS + 1] = L;                                   // codebook_loss
    out[Z_ELEMS + 2] = __fadd_rn(L, __fmul_rn(BETA, L));    // cluster_loss
    // perplexity
    float tot = 0.0f;
    for (int k = 0; k < KCODES; k++) tot = __fadd_rn(tot, (float)g_counts[k]);
    float denom = __fadd_rn(tot, EPS_F);
    float H = 0.0f;
    for (int k = 0; k < KCODES; k++) {
        float p = __fdiv_rn((float)g_counts[k], denom);
        H = __fadd_rn(H, __fmul_rn(p, __logf(__fadd_rn(p, EPS_F))));
    }
    out[Z_ELEMS + 3] = __expf(-H);
}

// ---------------------------------------------------------------------------
extern "C" void kernel_launch(void* const* d_in, const int* in_sizes, int n_in,
                              void* d_out, int out_size) {
    const float* z  = (const float*)d_in[0];   // [65536, 256]
    const float* cb = (const float*)d_in[1];   // [1024, 256]
    float* out = (float*)d_out;

    // zs (64KB) + 2 x 16KB stage buffers = 96KB dynamic smem
    static_assert(TT * DDIM * 4 + 2 * (DC / 4) * KC * 16 == 98304, "smem size");
    cudaFuncSetAttribute(vq_argmin, cudaFuncAttributeMaxDynamicSharedMemorySize, 98304);

    vq_init_kernel<<<4, 256>>>();
    vq_prep_cb_kernel<<<4, 256>>>(cb);
    vq_prep_z2_kernel<<<TOKENS / 32, 256>>>(z);
    vq_argmin<<<NBLK_A, 256, 98304>>>(z, cb, out);
    vq_finalize<<<1, 1>>>(out);
}